// round 1
// baseline (speedup 1.0000x reference)
#include <cuda_runtime.h>

#define NB 4
#define PRE 512
#define NC 2048
#define TANCH 261120

// ---------------- scratch (device globals; no allocation) ----------------
__device__ float g_topval[NB][4][PRE];
__device__ int   g_topidx[NB][4][PRE];
__device__ float g_box[NB][NC][5];
__device__ float g_score[NB][NC];
__device__ unsigned char g_valid[NB][NC];
__device__ unsigned long long g_key[NB][NC];
__device__ float g_sbox[NB][NC][5];
__device__ float g_sscore[NB][NC];
__device__ unsigned char g_svalid[NB][NC];
__device__ float g_geom[NB][NC][12];   // x0,y0,...,x3,y3, area, cx, cy, r
__device__ unsigned long long g_mask[NB][NC][32];
__device__ int g_keep[NB][PRE];
__device__ int g_nkeep[NB];

__device__ const int c_aoff[4] = {0, 196608, 245760, 258048};

__device__ __forceinline__ unsigned fflip(float f) {
    unsigned u = __float_as_uint(f);
    return (u & 0x80000000u) ? ~u : (u | 0x80000000u);
}
__device__ __forceinline__ float funflip(unsigned u) {
    return __uint_as_float((u & 0x80000000u) ? (u ^ 0x80000000u) : ~u);
}

// ---------------- stage 1: exact per-(image,level) top-512 ----------------
// one block per (b,lvl): 4-pass MSB radix select -> threshold key, then
// compaction (strict-greater + equal-with-lowest-index) + bitonic sort by
// (value desc, index asc). index = flattened (y*W+x)*A + a order.
__global__ __launch_bounds__(1024) void topk_kernel(const float* o0, const float* o1,
                                                    const float* o2, const float* o3) {
    int task = blockIdx.x;
    int b = task >> 2, lvl = task & 3;
    const float* base = lvl == 0 ? o0 : lvl == 1 ? o1 : lvl == 2 ? o2 : o3;
    int H = 256 >> lvl;
    int HW = H * H;
    int N = 3 * HW;
    const float* p = base + (long long)b * N;

    __shared__ int hist[256];
    __shared__ unsigned s_pref;
    __shared__ int s_k;
    unsigned prefix = 0;
    int k = PRE;
    for (int pass = 0; pass < 4; pass++) {
        int shift = 24 - 8 * pass;
        for (int i = threadIdx.x; i < 256; i += blockDim.x) hist[i] = 0;
        __syncthreads();
        unsigned dmask = (pass == 0) ? 0u : (0xFFFFFFFFu << (shift + 8));
        for (int m = threadIdx.x; m < N; m += blockDim.x) {
            unsigned u = fflip(p[m]);
            if ((u & dmask) == prefix) atomicAdd(&hist[(u >> shift) & 255], 1);
        }
        __syncthreads();
        if (threadIdx.x == 0) {
            int cum = 0, bin = 255;
            for (; bin > 0; --bin) {
                if (cum + hist[bin] >= k) break;
                cum += hist[bin];
            }
            s_pref = prefix | ((unsigned)bin << shift);
            s_k = k - cum;
        }
        __syncthreads();
        prefix = s_pref;
        k = s_k;
        __syncthreads();
    }

    __shared__ int cG, cE;
    __shared__ unsigned sval[PRE];
    __shared__ int sidx[PRE];
    __shared__ int eidx[256];
    if (threadIdx.x == 0) { cG = 0; cE = 0; }
    __syncthreads();
    for (int m = threadIdx.x; m < N; m += blockDim.x) {
        unsigned u = fflip(p[m]);
        if (u > prefix) {
            int s = atomicAdd(&cG, 1);
            if (s < PRE) { sval[s] = u; sidx[s] = (m % HW) * 3 + m / HW; }
        } else if (u == prefix) {
            int s = atomicAdd(&cE, 1);
            if (s < 256) eidx[s] = (m % HW) * 3 + m / HW;
        }
    }
    __syncthreads();
    if (threadIdx.x == 0) {
        int ne = cE < 256 ? cE : 256;
        int base2 = cG < PRE ? cG : PRE;  // cG < PRE always (strictly-greater count)
        // take k equal-valued entries with lowest flattened index
        for (int r = 0; r < k && r < ne && base2 + r < PRE; r++) {
            int mb = r;
            for (int j = r + 1; j < ne; j++)
                if (eidx[j] < eidx[mb]) mb = j;
            int tv = eidx[r]; eidx[r] = eidx[mb]; eidx[mb] = tv;
            sval[base2 + r] = prefix;
            sidx[base2 + r] = eidx[r];
        }
    }
    __syncthreads();

    __shared__ unsigned long long sk[PRE];
    for (int i = threadIdx.x; i < PRE; i += blockDim.x)
        sk[i] = (((unsigned long long)sval[i]) << 32) | (unsigned)(~sidx[i]);
    __syncthreads();
    for (int ksz = 2; ksz <= PRE; ksz <<= 1) {
        for (int j = ksz >> 1; j > 0; j >>= 1) {
            int i = threadIdx.x;
            if (i < PRE) {
                int l = i ^ j;
                if (l > i) {
                    unsigned long long a = sk[i], c = sk[l];
                    bool desc = ((i & ksz) == 0);
                    bool sw = desc ? (a < c) : (a > c);
                    if (sw) { sk[i] = c; sk[l] = a; }
                }
            }
            __syncthreads();
        }
    }
    for (int i = threadIdx.x; i < PRE; i += blockDim.x) {
        unsigned long long kk = sk[i];
        g_topval[b][lvl][i] = funflip((unsigned)(kk >> 32));
        g_topidx[b][lvl][i] = (int)(~(unsigned)(kk & 0xFFFFFFFFull));
    }
}

// ---------------- stage 2: gather + decode 2048 candidates/image ----------
__global__ void decode_kernel(const float* d0, const float* d1, const float* d2,
                              const float* d3, const float* anchors) {
    int g = blockIdx.x * blockDim.x + threadIdx.x;
    if (g >= NB * NC) return;
    int b = g >> 11, pos = g & (NC - 1);
    int lvl = pos >> 9, r = pos & 511;
    float val = g_topval[b][lvl][r];
    int li = g_topidx[b][lvl][r];
    int H = 256 >> lvl, HW = H * H;
    int a = li % 3, cell = li / 3;
    int x = cell % H, y = cell / H;
    const float* dl = lvl == 0 ? d0 : lvl == 1 ? d1 : lvl == 2 ? d2 : d3;
    long long bi = ((long long)b * 18 + a * 6) * HW + (long long)y * H + x;
    float dx = dl[bi], dy = dl[bi + HW], dw = dl[bi + 2LL * HW],
          dh = dl[bi + 3LL * HW], ds = dl[bi + 4LL * HW], dc = dl[bi + 5LL * HW];
    int t = c_aoff[lvl] + li;
    const float* an = anchors + ((long long)b * TANCH + t) * 5;
    float ax = an[0], ay = an[1], aw = an[2], ah = an[3], aa = an[4];
    const float LOGM = 4.135166556742356f;
    dw = fminf(dw, LOGM);
    dh = fminf(dh, LOGM);
    float bw = aw * expf(dw), bh = ah * expf(dh);
    float bcx = ax + dx * aw, bcy = ay + dy * ah;
    float ang = aa + atan2f(ds, dc);
    float sc = 0.5f + 0.5f * tanhf(0.5f * val);  // XLA logistic form
    bool vd = (bw >= 1e-3f) && (bh >= 1e-3f) && (sc >= 0.0f);
    g_box[b][pos][0] = bcx; g_box[b][pos][1] = bcy;
    g_box[b][pos][2] = bw;  g_box[b][pos][3] = bh;
    g_box[b][pos][4] = ang;
    g_score[b][pos] = sc;
    g_valid[b][pos] = vd ? 1 : 0;
    unsigned u = vd ? __float_as_uint(sc) : 0u;  // score desc, pos asc tiebreak
    g_key[b][pos] = (((unsigned long long)u) << 32) | (unsigned)(2047 - pos);
}

// ---------------- stage 3: per-image sort + geometry -----------------------
__global__ __launch_bounds__(1024) void sort_geom_kernel() {
    int b = blockIdx.x;
    __shared__ unsigned long long sk[NC];
    for (int i = threadIdx.x; i < NC; i += blockDim.x) sk[i] = g_key[b][i];
    __syncthreads();
    for (int ksz = 2; ksz <= NC; ksz <<= 1) {
        for (int j = ksz >> 1; j > 0; j >>= 1) {
            for (int i = threadIdx.x; i < NC; i += blockDim.x) {
                int l = i ^ j;
                if (l > i) {
                    unsigned long long a = sk[i], c = sk[l];
                    bool desc = ((i & ksz) == 0);
                    bool sw = desc ? (a < c) : (a > c);
                    if (sw) { sk[i] = c; sk[l] = a; }
                }
            }
            __syncthreads();
        }
    }
    for (int i = threadIdx.x; i < NC; i += blockDim.x) {
        int pos = 2047 - (int)(unsigned)(sk[i] & 0xFFFFFFFFull);
        int lvl = pos >> 9;
        float b0 = g_box[b][pos][0], b1 = g_box[b][pos][1];
        float w = g_box[b][pos][2], h = g_box[b][pos][3], ang = g_box[b][pos][4];
        g_sbox[b][i][0] = b0; g_sbox[b][i][1] = b1;
        g_sbox[b][i][2] = w;  g_sbox[b][i][3] = h;  g_sbox[b][i][4] = ang;
        unsigned char vd = g_valid[b][pos];
        g_svalid[b][i] = vd;
        g_sscore[b][i] = vd ? g_score[b][pos] : __int_as_float(0xff800000);
        float off = 8192.0f * (float)lvl;
        float cx = b0 + off, cy = b1 + off;
        float ca = cosf(ang), sa = sinf(ang);
        float hw = 0.5f * w, hh = 0.5f * h;
        float dxs[4] = {hw, -hw, -hw, hw};
        float dys[4] = {hh, hh, -hh, -hh};
#pragma unroll
        for (int c = 0; c < 4; c++) {
            g_geom[b][i][2 * c] = cx + dxs[c] * ca - dys[c] * sa;
            g_geom[b][i][2 * c + 1] = cy + dxs[c] * sa + dys[c] * ca;
        }
        g_geom[b][i][8] = w * h;
        g_geom[b][i][9] = cx;
        g_geom[b][i][10] = cy;
        g_geom[b][i][11] = 0.5f * sqrtf(w * w + h * h);
    }
}

// ---------------- stage 4: rotated IoU suppression bitmask -----------------
// Sutherland-Hodgman clip of quad P (row, subject) by quad Q (col, clipper),
// matching the reference's arithmetic (d>=0 interior, t = d/den, den==0 -> 1).
__device__ float inter_area(const float* P, const float* Q) {
    float px[8], py[8];
    int cnt = 4;
#pragma unroll
    for (int i = 0; i < 4; i++) { px[i] = P[2 * i]; py[i] = P[2 * i + 1]; }
    for (int kk = 0; kk < 4; kk++) {
        float p1x = Q[2 * kk], p1y = Q[2 * kk + 1];
        int k2 = (kk + 1) & 3;
        float ex = Q[2 * k2] - p1x, ey = Q[2 * k2 + 1] - p1y;
        float d[8];
        for (int i = 0; i < cnt; i++) d[i] = ex * (py[i] - p1y) - ey * (px[i] - p1x);
        float qx[8], qy[8];
        int oc = 0;
        for (int i = 0; i < cnt; i++) {
            int nx = (i + 1 < cnt) ? (i + 1) : 0;
            bool ci = d[i] >= 0.f, ni = d[nx] >= 0.f;
            if (ci) { if (oc < 8) { qx[oc] = px[i]; qy[oc] = py[i]; } oc++; }
            if (ci != ni) {
                float den = d[i] - d[nx];
                float t = d[i] / ((den == 0.f) ? 1.f : den);
                if (oc < 8) {
                    qx[oc] = px[i] + t * (px[nx] - px[i]);
                    qy[oc] = py[i] + t * (py[nx] - py[i]);
                }
                oc++;
            }
        }
        cnt = oc > 8 ? 8 : oc;
        for (int i = 0; i < cnt; i++) { px[i] = qx[i]; py[i] = qy[i]; }
        if (cnt == 0) break;
    }
    if (cnt < 3) return 0.f;
    float s = 0.f;
    for (int i = 0; i < cnt; i++) {
        int nx = (i + 1 < cnt) ? (i + 1) : 0;
        s += px[i] * py[nx] - px[nx] * py[i];
    }
    return 0.5f * fabsf(s);
}

__global__ void mask_kernel() {
    int b = blockIdx.z, rb = blockIdx.y, cb = blockIdx.x;
    int t = threadIdx.x;
    int row = rb * 64 + t;
    __shared__ float sg[64][12];
    unsigned long long bits = 0;
    if (cb >= rb) {
        for (int i = t; i < 64 * 12; i += 64)
            sg[i / 12][i % 12] = g_geom[b][cb * 64 + i / 12][i % 12];
        __syncthreads();
        float rg[12];
#pragma unroll
        for (int q = 0; q < 12; q++) rg[q] = g_geom[b][row][q];
        int j0 = (cb == rb) ? t + 1 : 0;
        for (int j = j0; j < 64; j++) {
            const float* cg = sg[j];
            float ddx = rg[9] - cg[9], ddy = rg[10] - cg[10];
            float rr = rg[11] + cg[11];
            if (ddx * ddx + ddy * ddy >= rr * rr) continue;   // disjoint => IoU 0
            float ai = rg[8], aj = cg[8];
            float mn = fminf(ai, aj), mx = fmaxf(ai, aj);
            if (mn <= 0.7f * mx) continue;                    // IoU<=0.7 bound
            float inter = inter_area(rg, cg);
            float iou = inter / (ai + aj - inter + 1e-7f);
            if (iou > 0.7f) bits |= (1ull << j);
        }
    }
    g_mask[b][row][cb] = bits;
}

// ---------------- stage 5: greedy scan (1 warp / image) --------------------
__global__ void greedy_kernel() {
    int b = blockIdx.x;
    int lane = threadIdx.x;  // 32 lanes, each owns one 64-bit word
    unsigned long long remv = 0;
    for (int j = 0; j < 64; j++)
        if (!g_svalid[b][lane * 64 + j]) remv |= (1ull << j);
    int n = 0;
    for (int i = 0; i < NC; i++) {
        unsigned long long w = __shfl_sync(0xffffffffu, remv, (i >> 6));
        if (!((w >> (i & 63)) & 1ull)) {
            if (lane == 0 && n < PRE) g_keep[b][n] = i;
            n++;
            remv |= g_mask[b][i][lane];
        }
    }
    if (lane == 0) g_nkeep[b] = n < PRE ? n : PRE;
}

// ---------------- stage 6: emit padded output ------------------------------
// layout: boxes [B,512,5] flattened, then scores [B,512]
__global__ void output_kernel(float* out) {
    int g = blockIdx.x * blockDim.x + threadIdx.x;
    if (g >= NB * PRE) return;
    int b = g >> 9, slot = g & 511;
    float v0 = 0, v1 = 0, v2 = 0, v3 = 0, v4 = 0, sc = 0;
    if (slot < g_nkeep[b]) {
        int i = g_keep[b][slot];
        v0 = g_sbox[b][i][0]; v1 = g_sbox[b][i][1];
        v2 = g_sbox[b][i][2]; v3 = g_sbox[b][i][3];
        v4 = g_sbox[b][i][4];
        sc = g_sscore[b][i];
    }
    float* ob = out + ((long long)b * PRE + slot) * 5;
    ob[0] = v0; ob[1] = v1; ob[2] = v2; ob[3] = v3; ob[4] = v4;
    out[NB * PRE * 5 + b * PRE + slot] = sc;
}

extern "C" void kernel_launch(void* const* d_in, const int* in_sizes, int n_in,
                              void* d_out, int out_size) {
    const float* obj[4] = {0, 0, 0, 0};
    const float* dlt[4] = {0, 0, 0, 0};
    const float* anch = 0;
    const int osz[4] = {786432, 196608, 49152, 12288};   // [B,3,H,H]
    const int dsz[4] = {4718592, 1179648, 294912, 73728}; // [B,18,H,H]
    for (int i = 0; i < n_in; i++) {
        int s = in_sizes[i];
        const float* p = (const float*)d_in[i];
        if (s == 5222400) { anch = p; continue; }
        for (int l = 0; l < 4; l++) {
            if (s == osz[l]) obj[l] = p;
            else if (s == dsz[l]) dlt[l] = p;
        }
    }
    topk_kernel<<<16, 1024>>>(obj[0], obj[1], obj[2], obj[3]);
    decode_kernel<<<8, 1024>>>(dlt[0], dlt[1], dlt[2], dlt[3], anch);
    sort_geom_kernel<<<NB, 1024>>>();
    mask_kernel<<<dim3(32, 32, NB), 64>>>();
    greedy_kernel<<<NB, 32>>>();
    output_kernel<<<(NB * PRE + 255) / 256, 256>>>((float*)d_out);
}

// round 2
// speedup vs baseline: 4.0343x; 4.0343x over previous
#include <cuda_runtime.h>

#define NB 4
#define PRE 512
#define NC 2048
#define TANCH 261120
#define NBIN 8192
#define CANDCAP 2048

// ---------------- scratch (device globals; no allocation) ----------------
__device__ int g_hist[16][NBIN];
__device__ int g_ccnt[16];
__device__ unsigned g_th[16];
__device__ unsigned long long g_cand[16][CANDCAP];
__device__ float g_topval[NB][4][PRE];
__device__ int   g_topidx[NB][4][PRE];
__device__ float g_box[NB][NC][5];
__device__ float g_score[NB][NC];
__device__ unsigned char g_valid[NB][NC];
__device__ unsigned long long g_key[NB][NC];
__device__ float g_sbox[NB][NC][5];
__device__ float g_sscore[NB][NC];
__device__ unsigned char g_svalid[NB][NC];
__device__ float g_geom[NB][NC][16];   // x0..y3, area, cx, cy, r, xmin,xmax,ymin,ymax
__device__ unsigned long long g_mask[NB][NC][32];
__device__ int g_keep[NB][PRE];
__device__ int g_nkeep[NB];

__device__ const int c_aoff[4] = {0, 196608, 245760, 258048};

__device__ __forceinline__ unsigned fflip(float f) {
    unsigned u = __float_as_uint(f);
    return (u & 0x80000000u) ? ~u : (u | 0x80000000u);
}
__device__ __forceinline__ float funflip(unsigned u) {
    return __uint_as_float((u & 0x80000000u) ? (u ^ 0x80000000u) : ~u);
}

// block mapping for full-grid scans: 33 blocks per image
// lvl0: 24 x 8192, lvl1: 6 x 8192, lvl2: 2 x 6144, lvl3: 1 x 3072
__device__ __forceinline__ void map_block(int bx, int& b, int& lvl, int& c0, int& n) {
    b = bx / 33;
    int t = bx % 33;
    if (t < 24)      { lvl = 0; c0 = t * 8192;        n = 8192; }
    else if (t < 30) { lvl = 1; c0 = (t - 24) * 8192; n = 8192; }
    else if (t < 32) { lvl = 2; c0 = (t - 30) * 6144; n = 6144; }
    else             { lvl = 3; c0 = 0;               n = 3072; }
}

__global__ void reset_kernel() {
    int g = blockIdx.x * blockDim.x + threadIdx.x;
    int* h = &g_hist[0][0];
    for (int i = g; i < 16 * NBIN; i += gridDim.x * blockDim.x) h[i] = 0;
    if (g < 16) g_ccnt[g] = 0;
}

// ---------------- stage 1a: 13-bit histogram (one full scan) --------------
__global__ __launch_bounds__(256) void hist_kernel(const float* __restrict__ o0,
                                                   const float* __restrict__ o1,
                                                   const float* __restrict__ o2,
                                                   const float* __restrict__ o3) {
    __shared__ int h[NBIN];
    for (int i = threadIdx.x; i < NBIN; i += 256) h[i] = 0;
    __syncthreads();
    int b, lvl, c0, n;
    map_block(blockIdx.x, b, lvl, c0, n);
    const float* base = lvl == 0 ? o0 : lvl == 1 ? o1 : lvl == 2 ? o2 : o3;
    int NL = 3 * (256 >> lvl) * (256 >> lvl);
    const float* p = base + (long long)b * NL + c0;
    for (int m = threadIdx.x; m < n; m += 256)
        atomicAdd(&h[fflip(p[m]) >> 19], 1);
    __syncthreads();
    int seg = b * 4 + lvl;
    for (int i = threadIdx.x; i < NBIN; i += 256)
        if (h[i]) atomicAdd(&g_hist[seg][i], h[i]);
}

// ---------------- stage 1b: threshold bin per segment ---------------------
__global__ __launch_bounds__(256) void thresh_kernel() {
    int seg = blockIdx.x;
    int t = threadIdx.x;
    __shared__ int part[256];
    int s = 0;
#pragma unroll 4
    for (int k = 0; k < 32; k++) s += g_hist[seg][NBIN - 1 - t * 32 - k];
    part[t] = s;
    __syncthreads();
    if (t == 0) {
        int cum = 0, th = 0;
        for (int c = 0; c < 256; c++) {
            if (cum + part[c] >= PRE) {
                int c2 = cum;
                for (int k = 0; k < 32; k++) {
                    int bin = NBIN - 1 - c * 32 - k;
                    c2 += g_hist[seg][bin];
                    if (c2 >= PRE) { th = bin; break; }
                }
                break;
            }
            cum += part[c];
        }
        g_th[seg] = (unsigned)th;
    }
}

// ---------------- stage 1c: collect candidates (second full scan) ---------
__global__ __launch_bounds__(256) void collect_kernel(const float* __restrict__ o0,
                                                      const float* __restrict__ o1,
                                                      const float* __restrict__ o2,
                                                      const float* __restrict__ o3) {
    int b, lvl, c0, n;
    map_block(blockIdx.x, b, lvl, c0, n);
    const float* base = lvl == 0 ? o0 : lvl == 1 ? o1 : lvl == 2 ? o2 : o3;
    int H = 256 >> lvl, HW = H * H;
    int NL = 3 * HW;
    int seg = b * 4 + lvl;
    unsigned th = g_th[seg];
    const float* p = base + (long long)b * NL + c0;
    for (int m = threadIdx.x; m < n; m += 256) {
        unsigned u = fflip(p[m]);
        if ((u >> 19) >= th) {
            int gm = c0 + m;                      // index within [A,H,W] slice
            int idx = (gm % HW) * 3 + gm / HW;    // flattened (y*W+x)*A + a
            int pos = atomicAdd(&g_ccnt[seg], 1);
            if (pos < CANDCAP)
                g_cand[seg][pos] = (((unsigned long long)u) << 32) | (unsigned)(~idx);
        }
    }
}

// ---------------- stage 1d: per-segment sort -> exact top-512 -------------
__global__ __launch_bounds__(1024) void sort16_kernel() {
    int seg = blockIdx.x;
    int b = seg >> 2, lvl = seg & 3;
    __shared__ unsigned long long sk[CANDCAP];
    int cnt = g_ccnt[seg];
    if (cnt > CANDCAP) cnt = CANDCAP;
    for (int i = threadIdx.x; i < CANDCAP; i += 1024)
        sk[i] = (i < cnt) ? g_cand[seg][i] : 0ull;
    __syncthreads();
    for (int ksz = 2; ksz <= CANDCAP; ksz <<= 1) {
        for (int j = ksz >> 1; j > 0; j >>= 1) {
            for (int i = threadIdx.x; i < CANDCAP; i += 1024) {
                int l = i ^ j;
                if (l > i) {
                    unsigned long long a = sk[i], c = sk[l];
                    bool desc = ((i & ksz) == 0);
                    if (desc ? (a < c) : (a > c)) { sk[i] = c; sk[l] = a; }
                }
            }
            __syncthreads();
        }
    }
    if (threadIdx.x < PRE) {
        unsigned long long kk = sk[threadIdx.x];
        g_topval[b][lvl][threadIdx.x] = funflip((unsigned)(kk >> 32));
        g_topidx[b][lvl][threadIdx.x] = (int)(~(unsigned)(kk & 0xFFFFFFFFull));
    }
}

// ---------------- stage 2: gather + decode 2048 candidates/image ----------
__global__ void decode_kernel(const float* __restrict__ d0, const float* __restrict__ d1,
                              const float* __restrict__ d2, const float* __restrict__ d3,
                              const float* __restrict__ anchors) {
    int g = blockIdx.x * blockDim.x + threadIdx.x;
    if (g >= NB * NC) return;
    int b = g >> 11, pos = g & (NC - 1);
    int lvl = pos >> 9, r = pos & 511;
    float val = g_topval[b][lvl][r];
    int li = g_topidx[b][lvl][r];
    int H = 256 >> lvl, HW = H * H;
    int a = li % 3, cell = li / 3;
    int x = cell % H, y = cell / H;
    const float* dl = lvl == 0 ? d0 : lvl == 1 ? d1 : lvl == 2 ? d2 : d3;
    long long bi = ((long long)b * 18 + a * 6) * HW + (long long)y * H + x;
    float dx = dl[bi], dy = dl[bi + HW], dw = dl[bi + 2LL * HW],
          dh = dl[bi + 3LL * HW], ds = dl[bi + 4LL * HW], dc = dl[bi + 5LL * HW];
    int t = c_aoff[lvl] + li;
    const float* an = anchors + ((long long)b * TANCH + t) * 5;
    float ax = an[0], ay = an[1], aw = an[2], ah = an[3], aa = an[4];
    const float LOGM = 4.135166556742356f;
    dw = fminf(dw, LOGM);
    dh = fminf(dh, LOGM);
    float bw = aw * expf(dw), bh = ah * expf(dh);
    float bcx = ax + dx * aw, bcy = ay + dy * ah;
    float ang = aa + atan2f(ds, dc);
    float sc = 0.5f + 0.5f * tanhf(0.5f * val);
    bool vd = (bw >= 1e-3f) && (bh >= 1e-3f) && (sc >= 0.0f);
    g_box[b][pos][0] = bcx; g_box[b][pos][1] = bcy;
    g_box[b][pos][2] = bw;  g_box[b][pos][3] = bh;
    g_box[b][pos][4] = ang;
    g_score[b][pos] = sc;
    g_valid[b][pos] = vd ? 1 : 0;
    unsigned u = vd ? __float_as_uint(sc) : 0u;
    g_key[b][pos] = (((unsigned long long)u) << 32) | (unsigned)(2047 - pos);
}

// ---------------- stage 3: per-image sort + geometry -----------------------
__global__ __launch_bounds__(1024) void sort_geom_kernel() {
    int b = blockIdx.x;
    __shared__ unsigned long long sk[NC];
    for (int i = threadIdx.x; i < NC; i += 1024) sk[i] = g_key[b][i];
    __syncthreads();
    for (int ksz = 2; ksz <= NC; ksz <<= 1) {
        for (int j = ksz >> 1; j > 0; j >>= 1) {
            for (int i = threadIdx.x; i < NC; i += 1024) {
                int l = i ^ j;
                if (l > i) {
                    unsigned long long a = sk[i], c = sk[l];
                    bool desc = ((i & ksz) == 0);
                    if (desc ? (a < c) : (a > c)) { sk[i] = c; sk[l] = a; }
                }
            }
            __syncthreads();
        }
    }
    for (int i = threadIdx.x; i < NC; i += 1024) {
        int pos = 2047 - (int)(unsigned)(sk[i] & 0xFFFFFFFFull);
        int lvl = pos >> 9;
        float b0 = g_box[b][pos][0], b1 = g_box[b][pos][1];
        float w = g_box[b][pos][2], h = g_box[b][pos][3], ang = g_box[b][pos][4];
        g_sbox[b][i][0] = b0; g_sbox[b][i][1] = b1;
        g_sbox[b][i][2] = w;  g_sbox[b][i][3] = h;  g_sbox[b][i][4] = ang;
        unsigned char vd = g_valid[b][pos];
        g_svalid[b][i] = vd;
        g_sscore[b][i] = vd ? g_score[b][pos] : __int_as_float(0xff800000);
        float off = 8192.0f * (float)lvl;
        float cx = b0 + off, cy = b1 + off;
        float ca = cosf(ang), sa = sinf(ang);
        float hw = 0.5f * w, hh = 0.5f * h;
        float dxs[4] = {hw, -hw, -hw, hw};
        float dys[4] = {hh, hh, -hh, -hh};
        float xmn = 1e30f, xmx = -1e30f, ymn = 1e30f, ymx = -1e30f;
#pragma unroll
        for (int c = 0; c < 4; c++) {
            float xx = cx + dxs[c] * ca - dys[c] * sa;
            float yy = cy + dxs[c] * sa + dys[c] * ca;
            g_geom[b][i][2 * c] = xx;
            g_geom[b][i][2 * c + 1] = yy;
            xmn = fminf(xmn, xx); xmx = fmaxf(xmx, xx);
            ymn = fminf(ymn, yy); ymx = fmaxf(ymx, yy);
        }
        g_geom[b][i][8] = w * h;
        g_geom[b][i][9] = cx;
        g_geom[b][i][10] = cy;
        g_geom[b][i][11] = 0.5f * sqrtf(w * w + h * h);
        g_geom[b][i][12] = xmn;
        g_geom[b][i][13] = xmx;
        g_geom[b][i][14] = ymn;
        g_geom[b][i][15] = ymx;
    }
}

// ---------------- stage 4: rotated IoU suppression bitmask -----------------
__device__ float inter_area(float4 pA, float4 pB, float4 qA, float4 qB) {
    float px[8], py[8], ox[8], oy[8];
    px[0] = pA.x; py[0] = pA.y; px[1] = pA.z; py[1] = pA.w;
    px[2] = pB.x; py[2] = pB.y; px[3] = pB.z; py[3] = pB.w;
    float qx[4] = {qA.x, qA.z, qB.x, qB.z};
    float qy[4] = {qA.y, qA.w, qB.y, qB.w};
    int cnt = 4;
#pragma unroll
    for (int kk = 0; kk < 4; kk++) {
        float p1x = qx[kk], p1y = qy[kk];
        int k2 = (kk + 1) & 3;
        float ex = qx[k2] - p1x, ey = qy[k2] - p1y;
        int oc = 0;
        float d0 = ex * (py[0] - p1y) - ey * (px[0] - p1x);
        float dc = d0;
        for (int i = 0; i < cnt; i++) {
            int nx = (i + 1 < cnt) ? i + 1 : 0;
            float dn = (i + 1 < cnt) ? (ex * (py[i + 1] - p1y) - ey * (px[i + 1] - p1x)) : d0;
            bool ci = dc >= 0.f, ni = dn >= 0.f;
            if (ci) { ox[oc] = px[i]; oy[oc] = py[i]; oc++; }
            if (ci != ni) {
                float den = dc - dn;
                float tt = dc / ((den == 0.f) ? 1.f : den);
                ox[oc] = px[i] + tt * (px[nx] - px[i]);
                oy[oc] = py[i] + tt * (py[nx] - py[i]);
                oc++;
            }
            dc = dn;
        }
        cnt = oc;
        if (cnt == 0) break;
        for (int i = 0; i < cnt; i++) { px[i] = ox[i]; py[i] = oy[i]; }
    }
    if (cnt < 3) return 0.f;
    float s = 0.f;
    for (int i = 0; i < cnt; i++) {
        int nx = (i + 1 < cnt) ? i + 1 : 0;
        s += px[i] * py[nx] - px[nx] * py[i];
    }
    return 0.5f * fabsf(s);
}

__global__ __launch_bounds__(64) void mask_kernel() {
    int b = blockIdx.y;
    // decode triangular tile id -> (rb, cb) with cb >= rb
    int tt = blockIdx.x;
    int rb = 0, rowrem = 32;
    while (tt >= rowrem) { tt -= rowrem; rowrem--; rb++; }
    int cb = rb + tt;

    int t = threadIdx.x;
    int row = rb * 64 + t;
    __shared__ float4 sg[64][4];
    const float4* gg = (const float4*)&g_geom[b][0][0];
    for (int i = t; i < 256; i += 64)
        ((float4*)sg)[i] = gg[cb * 256 + i];
    __syncthreads();

    float4 rA = gg[row * 4 + 0];
    float4 rB = gg[row * 4 + 1];
    float4 rC = gg[row * 4 + 2];   // area, cx, cy, r
    float4 rD = gg[row * 4 + 3];   // xmin, xmax, ymin, ymax
    unsigned long long bits = 0;
    int j0 = (cb == rb) ? t + 1 : 0;
    for (int j = j0; j < 64; j++) {
        float4 cC = sg[j][2];
        float ddx = rC.y - cC.y, ddy = rC.z - cC.z;
        float rr = rC.w + cC.w;
        if (ddx * ddx + ddy * ddy >= rr * rr) continue;     // disjoint
        float ai = rC.x, aj = cC.x;
        float S = ai + aj;
        float mn = fminf(ai, aj), mx = fmaxf(ai, aj);
        if (mn <= 0.7f * mx) continue;                      // IoU<=0.7 bound
        float4 cD = sg[j][3];
        float xl = fmaxf(rD.x, cD.x), xr = fminf(rD.y, cD.y);
        float yl = fmaxf(rD.z, cD.z), yr = fminf(rD.w, cD.w);
        float ub = fmaxf(xr - xl, 0.f) * fmaxf(yr - yl, 0.f);
        if (ub * 1.7f < S * 0.6993f) continue;              // AABB bound (safety 1e-3)
        float inter = inter_area(rA, rB, sg[j][0], sg[j][1]);
        float iou = inter / (S - inter + 1e-7f);
        if (iou > 0.7f) bits |= (1ull << j);
    }
    g_mask[b][row][cb] = bits;
}

// ---------------- stage 5: greedy scan (1 warp / image) --------------------
__global__ void greedy_kernel() {
    int b = blockIdx.x;
    int lane = threadIdx.x;
    unsigned long long remv = 0;
    for (int j = 0; j < 64; j++)
        if (!g_svalid[b][lane * 64 + j]) remv |= (1ull << j);
    int n = 0;
    unsigned long long nextw = g_mask[b][0][lane];
    for (int i = 0; i < NC; i++) {
        unsigned long long cur = nextw;
        if (i + 1 < NC) nextw = g_mask[b][i + 1][lane];     // unconditional prefetch
        unsigned long long w = __shfl_sync(0xffffffffu, remv, (i >> 6));
        if (!((w >> (i & 63)) & 1ull)) {
            if (lane == 0) g_keep[b][n] = i;
            n++;
            remv |= cur;
            if (n >= PRE) break;
        }
    }
    if (lane == 0) g_nkeep[b] = n;
}

// ---------------- stage 6: emit padded output ------------------------------
__global__ void output_kernel(float* out) {
    int g = blockIdx.x * blockDim.x + threadIdx.x;
    if (g >= NB * PRE) return;
    int b = g >> 9, slot = g & 511;
    float v0 = 0, v1 = 0, v2 = 0, v3 = 0, v4 = 0, sc = 0;
    if (slot < g_nkeep[b]) {
        int i = g_keep[b][slot];
        v0 = g_sbox[b][i][0]; v1 = g_sbox[b][i][1];
        v2 = g_sbox[b][i][2]; v3 = g_sbox[b][i][3];
        v4 = g_sbox[b][i][4];
        sc = g_sscore[b][i];
    }
    float* ob = out + ((long long)b * PRE + slot) * 5;
    ob[0] = v0; ob[1] = v1; ob[2] = v2; ob[3] = v3; ob[4] = v4;
    out[NB * PRE * 5 + b * PRE + slot] = sc;
}

extern "C" void kernel_launch(void* const* d_in, const int* in_sizes, int n_in,
                              void* d_out, int out_size) {
    const float* obj[4] = {0, 0, 0, 0};
    const float* dlt[4] = {0, 0, 0, 0};
    const float* anch = 0;
    const int osz[4] = {786432, 196608, 49152, 12288};
    const int dsz[4] = {4718592, 1179648, 294912, 73728};
    for (int i = 0; i < n_in; i++) {
        int s = in_sizes[i];
        const float* p = (const float*)d_in[i];
        if (s == 5222400) { anch = p; continue; }
        for (int l = 0; l < 4; l++) {
            if (s == osz[l]) obj[l] = p;
            else if (s == dsz[l]) dlt[l] = p;
        }
    }
    reset_kernel<<<128, 256>>>();
    hist_kernel<<<132, 256>>>(obj[0], obj[1], obj[2], obj[3]);
    thresh_kernel<<<16, 256>>>();
    collect_kernel<<<132, 256>>>(obj[0], obj[1], obj[2], obj[3]);
    sort16_kernel<<<16, 1024>>>();
    decode_kernel<<<8, 1024>>>(dlt[0], dlt[1], dlt[2], dlt[3], anch);
    sort_geom_kernel<<<NB, 1024>>>();
    mask_kernel<<<dim3(528, NB), 64>>>();
    greedy_kernel<<<NB, 32>>>();
    output_kernel<<<(NB * PRE + 255) / 256, 256>>>((float*)d_out);
}